// round 14
// baseline (speedup 1.0000x reference)
#include <cuda_runtime.h>
#include <cuda_bf16.h>
#include <math.h>
#include <stdint.h>

// ---------------------------------------------------------------------------
// Problem constants
// ---------------------------------------------------------------------------
#define NMAX 50000
#define EMAX 800000
#define F_IN 256
#define HDIM 128
#define DDIM 64
#define PDIM 512   // 8 projections x 64

// Packed projection layout within a row of P (word offsets):
//   [0..255]   q/s blocks, pairwise interleave: lane l float2 = dims (l, l+32)
//     QMU @0, SMU @64, QLS @128, SLS @192
//   [256..383] KK block: lane l float4 @ word 256+4l = (kmu_l, kmu_{l+32}, kls_l, kls_{l+32})
//   [384..511] VV block: lane l float4 @ word 384+4l = (vmu_l, vmu_{l+32}, vls_l, vls_{l+32})
#define OFF_QMU 0
#define OFF_SMU 64
#define OFF_QLS 128
#define OFF_SLS 192
#define OFF_KK  256
#define OFF_VV  384

// ---------------------------------------------------------------------------
// Static device scratch
// ---------------------------------------------------------------------------
__device__ int      g_is64;
__device__ int      g_cnt[NMAX];
__device__ int      g_pref[NMAX];
__device__ int      g_bsum[64];
__device__ int      g_rowptr[NMAX + 1];
__device__ int      g_cursor[NMAX];
__device__ int      g_src32[EMAX];
__device__ int      g_dst32[EMAX];
__device__ int      g_csr_src[EMAX];
__device__ float    g_dinv[NMAX];
__device__ float    g_h0[(size_t)NMAX * HDIM];   // x @ W_gcn (fp32)
__device__ uint32_t g_h [(size_t)NMAX * HDIM];   // leaky(agg)+b as tf32 bits
__device__ float    g_P [(size_t)NMAX * PDIM];   // packed projections
__device__ uint32_t g_Wcat[HDIM * PDIM];         // tf32 bits
__device__ float    g_bcat[PDIM];

__device__ __forceinline__ uint32_t f2tf32(float v) {
    uint32_t o;
    asm volatile("cvt.rna.tf32.f32 %0, %1;" : "=r"(o) : "f"(v));
    return o;
}

// ---------------------------------------------------------------------------
// Edge dtype detection
// ---------------------------------------------------------------------------
__global__ void detect_dtype_kernel(const int* __restrict__ w, int e) {
    __shared__ int s[256];
    int t = threadIdx.x;
    int limit = (e < 256) ? e : 256;
    int nz = 0;
    if (t < limit) nz = (w[2 * t + 1] != 0) ? 1 : 0;
    s[t] = nz;
    __syncthreads();
    for (int o = 128; o; o >>= 1) {
        if (t < o) s[t] += s[t + o];
        __syncthreads();
    }
    if (t == 0) g_is64 = (s[0] == 0) ? 1 : 0;
}

__global__ void zero_cnt_kernel(int n) {
    int i = blockIdx.x * blockDim.x + threadIdx.x;
    if (i < n) g_cnt[i] = 0;
}

__global__ void edge_prep_kernel(const void* __restrict__ ei, int e, int n) {
    int idx = blockIdx.x * blockDim.x + threadIdx.x;
    if (idx >= e) return;
    int s, d;
    if (g_is64) {
        const long long* p = (const long long*)ei;
        s = (int)p[idx];
        d = (int)p[idx + e];
    } else {
        const int* p = (const int*)ei;
        s = p[idx];
        d = p[idx + e];
    }
    s = (s < 0) ? 0 : ((s >= n) ? n - 1 : s);
    d = (d < 0) ? 0 : ((d >= n) ? n - 1 : d);
    g_src32[idx] = s;
    g_dst32[idx] = d;
    atomicAdd(&g_cnt[d], 1);
}

// ---------------------------------------------------------------------------
// Parallel scan (2 passes)
// ---------------------------------------------------------------------------
__global__ void scan_pass1_kernel(int n) {
    __shared__ int s[1024];
    int t = threadIdx.x;
    int i = blockIdx.x * 1024 + t;
    int v = (i < n) ? g_cnt[i] : 0;
    s[t] = v;
    __syncthreads();
    #pragma unroll
    for (int off = 1; off < 1024; off <<= 1) {
        int u = 0;
        if (t >= off) u = s[t - off];
        __syncthreads();
        if (t >= off) s[t] += u;
        __syncthreads();
    }
    if (i < n) g_pref[i] = s[t];
    if (t == 1023) g_bsum[blockIdx.x] = s[t];
}

__global__ void scan_pass2_kernel(int n) {
    __shared__ int sboff;
    int b = blockIdx.x;
    int t = threadIdx.x;
    if (t == 0) {
        int acc = 0;
        for (int j = 0; j < b; ++j) acc += g_bsum[j];
        sboff = acc;
    }
    __syncthreads();
    int i = b * 1024 + t;
    if (i < n) {
        int incl = g_pref[i] + sboff;
        int c = g_cnt[i];
        int excl = incl - c;
        g_rowptr[i] = excl;
        g_cursor[i] = excl;
        g_dinv[i] = rsqrtf((float)(c + 1));
        if (i == n - 1) g_rowptr[n] = incl;
    }
}

__global__ void fill_csr_kernel(int e) {
    int idx = blockIdx.x * blockDim.x + threadIdx.x;
    if (idx >= e) return;
    int d = g_dst32[idx];
    int pos = atomicAdd(&g_cursor[d], 1);
    g_csr_src[pos] = g_src32[idx];
}

// Pack weights into the P column layout described above. Wcat as tf32 bits.
__global__ void pack_weights_kernel(
    const float* Wq_mu, const float* Ws_mu, const float* Wq_ls, const float* Ws_ls,
    const float* Wk_mu, const float* Wv_mu, const float* Wk_ls, const float* Wv_ls,
    const float* bq_mu, const float* bs_mu, const float* bq_ls, const float* bs_ls,
    const float* bk_mu, const float* bv_mu, const float* bk_ls, const float* bv_ls) {
    int idx = blockIdx.x * blockDim.x + threadIdx.x;

    // map packed column j -> (source matrix index, source column)
    auto map_col = [&](int j, int& which, int& c) {
        if (j < 256) {
            int p4 = j / DDIM;            // 0..3 : qmu, smu, qls, sls
            int cp = j % DDIM;
            c = (cp >> 1) + 32 * (cp & 1);
            which = p4;                   // 0..3
        } else if (j < 384) {
            int tt = j - 256;
            int l = tt >> 2, r = tt & 3;
            c = l + 32 * (r & 1);
            which = (r < 2) ? 4 : 6;      // kmu : kls
        } else {
            int tt = j - 384;
            int l = tt >> 2, r = tt & 3;
            c = l + 32 * (r & 1);
            which = (r < 2) ? 5 : 7;      // vmu : vls
        }
    };
    const float* Ws[8] = {Wq_mu, Ws_mu, Wq_ls, Ws_ls, Wk_mu, Wv_mu, Wk_ls, Wv_ls};
    const float* bs[8] = {bq_mu, bs_mu, bq_ls, bs_ls, bk_mu, bv_mu, bk_ls, bv_ls};

    if (idx < HDIM * PDIM) {
        int k = idx / PDIM;
        int j = idx % PDIM;
        int which, c;
        map_col(j, which, c);
        g_Wcat[idx] = f2tf32(Ws[which][k * DDIM + c]);
    }
    if (idx < PDIM) {
        int which, c;
        map_col(idx, which, c);
        g_bcat[idx] = bs[which][c];
    }
}

// ---------------------------------------------------------------------------
// Shared MMA helper
// ---------------------------------------------------------------------------
__device__ __forceinline__ void mma_tf32(float* c,
    uint32_t a0, uint32_t a1, uint32_t a2, uint32_t a3,
    uint32_t b0, uint32_t b1) {
    asm volatile(
        "mma.sync.aligned.m16n8k8.row.col.f32.tf32.tf32.f32 "
        "{%0,%1,%2,%3}, {%4,%5,%6,%7}, {%8,%9}, {%0,%1,%2,%3};"
        : "+f"(c[0]), "+f"(c[1]), "+f"(c[2]), "+f"(c[3])
        : "r"(a0), "r"(a1), "r"(a2), "r"(a3), "r"(b0), "r"(b1));
}

// ---------------------------------------------------------------------------
// GEMM #1 (x @ W_gcn): proven engine, fp32 inputs with in-kernel cvt.
// ---------------------------------------------------------------------------
#define TM 128
#define TN 128
#define TK 32
#define SROW 136

__device__ __forceinline__ int a_colp(int m) {
    return ((m >> 4) << 4) + ((m & 7) << 1) + ((m >> 3) & 1);
}

__global__ __launch_bounds__(256) void gemm_xw_kernel(
    const float* __restrict__ A, const float* __restrict__ B, int M) {
    __shared__ __align__(16) uint32_t As[TK][SROW];
    __shared__ __align__(16) uint32_t Bs[TK][SROW];
    const int K = F_IN, NC = HDIM;

    int t = threadIdx.x;
    int lane = t & 31;
    int warp = t >> 5;
    int wm = warp >> 2;
    int wn = warp & 3;
    int g  = lane >> 2;
    int tg = lane & 3;

    int rowBlock = blockIdx.y * TM;
    int colBlock = blockIdx.x * TN;

    float c[4][4][4];
    #pragma unroll
    for (int i = 0; i < 4; ++i)
        #pragma unroll
        for (int j = 0; j < 4; ++j)
            #pragma unroll
            for (int k = 0; k < 4; ++k) c[i][j][k] = 0.f;

    for (int k0 = 0; k0 < K; k0 += TK) {
        #pragma unroll
        for (int l = 0; l < 4; ++l) {
            int lin = t + l * 256;
            int ar = lin >> 3;
            int ac = (lin & 7) << 2;
            int grow = rowBlock + ar;
            int cp = a_colp(ar);
            float4 v = make_float4(0.f, 0.f, 0.f, 0.f);
            if (grow < M)
                v = *(const float4*)&A[(size_t)grow * K + k0 + ac];
            As[ac + 0][cp] = f2tf32(v.x);
            As[ac + 1][cp] = f2tf32(v.y);
            As[ac + 2][cp] = f2tf32(v.z);
            As[ac + 3][cp] = f2tf32(v.w);
        }
        #pragma unroll
        for (int l = 0; l < 4; ++l) {
            int lin = t + l * 256;
            int br = lin >> 5;
            int bc = (lin & 31) << 2;
            float4 v = *(const float4*)&B[(size_t)(k0 + br) * NC + colBlock + bc];
            uint4 u;
            u.x = f2tf32(v.x); u.y = f2tf32(v.y);
            u.z = f2tf32(v.z); u.w = f2tf32(v.w);
            *(uint4*)&Bs[br][bc] = u;
        }
        __syncthreads();

        #pragma unroll
        for (int ks = 0; ks < 4; ++ks) {
            int kr = ks * 8 + tg;
            uint32_t a[4][4], b[4][2];
            #pragma unroll
            for (int mt = 0; mt < 4; ++mt) {
                int pcol = (wm * 4 + mt) * 16 + (g << 1);
                uint2 p0 = *(const uint2*)&As[kr][pcol];
                uint2 p1 = *(const uint2*)&As[kr + 4][pcol];
                a[mt][0] = p0.x; a[mt][1] = p0.y;
                a[mt][2] = p1.x; a[mt][3] = p1.y;
            }
            #pragma unroll
            for (int nt = 0; nt < 4; ++nt) {
                int nb = wn * 32 + nt * 8 + g;
                b[nt][0] = Bs[kr][nb];
                b[nt][1] = Bs[kr + 4][nb];
            }
            #pragma unroll
            for (int mt = 0; mt < 4; ++mt)
                #pragma unroll
                for (int nt = 0; nt < 4; ++nt)
                    mma_tf32(c[mt][nt], a[mt][0], a[mt][1], a[mt][2], a[mt][3],
                             b[nt][0], b[nt][1]);
        }
        __syncthreads();
    }

    #pragma unroll
    for (int mt = 0; mt < 4; ++mt) {
        #pragma unroll
        for (int nt = 0; nt < 4; ++nt) {
            int col = colBlock + wn * 32 + nt * 8 + tg * 2;
            int row0 = rowBlock + wm * 64 + mt * 16 + g;
            if (row0 < M) {
                float2 o = make_float2(c[mt][nt][0], c[mt][nt][1]);
                *(float2*)&g_h0[(size_t)row0 * NC + col] = o;
            }
            int row1 = row0 + 8;
            if (row1 < M) {
                float2 o = make_float2(c[mt][nt][2], c[mt][nt][3]);
                *(float2*)&g_h0[(size_t)row1 * NC + col] = o;
            }
        }
    }
}

// ---------------------------------------------------------------------------
// GEMM #2 (h @ Wcat, tf32 bits): 4-buffer cp.async pipeline (R13 engine).
// ---------------------------------------------------------------------------
#define PK 16
#define A_STR 20
#define B_STR 136
#define NSTAGE (HDIM / PK)      // 8
#define NBUF 4
#define A_BUF_WORDS (TM * A_STR)           // 2560
#define B_BUF_WORDS (PK * B_STR)           // 2176
#define PIPE_SMEM_BYTES (NBUF * (A_BUF_WORDS + B_BUF_WORDS) * 4)

__device__ __forceinline__ void cp_async16(uint32_t dst, const void* src, int srcBytes) {
    asm volatile("cp.async.cg.shared.global [%0], [%1], 16, %2;\n"
                 :: "r"(dst), "l"(src), "r"(srcBytes));
}
__device__ __forceinline__ void cp_commit() {
    asm volatile("cp.async.commit_group;\n");
}

__global__ __launch_bounds__(256) void gemm_proj_pipe_kernel(int M) {
    extern __shared__ __align__(16) uint32_t smem[];
    uint32_t* AsBuf = smem;
    uint32_t* BsBuf = smem + NBUF * A_BUF_WORDS;
    const uint32_t* A = g_h;
    const uint32_t* B = g_Wcat;
    const int K = HDIM, NC = PDIM;

    int t = threadIdx.x;
    int lane = t & 31;
    int warp = t >> 5;
    int wm = warp >> 2;
    int wn = warp & 3;
    int g  = lane >> 2;
    int tg = lane & 3;

    int rowBlock = blockIdx.y * TM;
    int colBlock = blockIdx.x * TN;

    uint32_t asBase = (uint32_t)__cvta_generic_to_shared(AsBuf);
    uint32_t bsBase = (uint32_t)__cvta_generic_to_shared(BsBuf);

    int a_r[2], a_c[2], b_r[2], b_c[2];
    #pragma unroll
    for (int l = 0; l < 2; ++l) {
        int lin = t + l * 256;
        a_r[l] = lin >> 2;
        a_c[l] = (lin & 3) << 2;
        b_r[l] = lin >> 5;
        b_c[l] = (lin & 31) << 2;
    }

    float c[4][4][4];
    #pragma unroll
    for (int i = 0; i < 4; ++i)
        #pragma unroll
        for (int j = 0; j < 4; ++j)
            #pragma unroll
            for (int k = 0; k < 4; ++k) c[i][j][k] = 0.f;

    #pragma unroll
    for (int p = 0; p < 3; ++p) {
        int k0 = p * PK;
        #pragma unroll
        for (int l = 0; l < 2; ++l) {
            int grow = rowBlock + a_r[l];
            int gr = (grow < M) ? grow : (M - 1);
            cp_async16(asBase + (((p * TM + a_r[l]) * A_STR + a_c[l]) << 2),
                       &A[(size_t)gr * K + k0 + a_c[l]], (grow < M) ? 16 : 0);
            cp_async16(bsBase + (((p * PK + b_r[l]) * B_STR + b_c[l]) << 2),
                       &B[(size_t)(k0 + b_r[l]) * NC + colBlock + b_c[l]], 16);
        }
        cp_commit();
    }

    #pragma unroll
    for (int s = 0; s < NSTAGE; ++s) {
        int cur = s & (NBUF - 1);
        asm volatile("cp.async.wait_group 2;\n");
        __syncthreads();

        const uint32_t* Acur = AsBuf + cur * A_BUF_WORDS;
        const uint32_t* Bcur = BsBuf + cur * B_BUF_WORDS;
        #pragma unroll
        for (int ks = 0; ks < 2; ++ks) {
            int kr = ks * 8 + tg;
            uint32_t a[4][4], b[4][2];
            #pragma unroll
            for (int mt = 0; mt < 4; ++mt) {
                int mb = wm * 64 + mt * 16 + g;
                a[mt][0] = Acur[mb * A_STR + kr];
                a[mt][1] = Acur[(mb + 8) * A_STR + kr];
                a[mt][2] = Acur[mb * A_STR + kr + 4];
                a[mt][3] = Acur[(mb + 8) * A_STR + kr + 4];
            }
            #pragma unroll
            for (int nt = 0; nt < 4; ++nt) {
                int nb = wn * 32 + nt * 8 + g;
                b[nt][0] = Bcur[kr * B_STR + nb];
                b[nt][1] = Bcur[(kr + 4) * B_STR + nb];
            }
            #pragma unroll
            for (int mt = 0; mt < 4; ++mt)
                #pragma unroll
                for (int nt = 0; nt < 4; ++nt)
                    mma_tf32(c[mt][nt], a[mt][0], a[mt][1], a[mt][2], a[mt][3],
                             b[nt][0], b[nt][1]);
        }
        __syncthreads();

        if (s + 3 < NSTAGE) {
            int nb_ = (s + 3) & (NBUF - 1);
            int k0 = (s + 3) * PK;
            #pragma unroll
            for (int l = 0; l < 2; ++l) {
                int grow = rowBlock + a_r[l];
                int gr = (grow < M) ? grow : (M - 1);
                cp_async16(asBase + (((nb_ * TM + a_r[l]) * A_STR + a_c[l]) << 2),
                           &A[(size_t)gr * K + k0 + a_c[l]], (grow < M) ? 16 : 0);
                cp_async16(bsBase + (((nb_ * PK + b_r[l]) * B_STR + b_c[l]) << 2),
                           &B[(size_t)(k0 + b_r[l]) * NC + colBlock + b_c[l]], 16);
            }
        }
        cp_commit();
    }

    #pragma unroll
    for (int mt = 0; mt < 4; ++mt) {
        #pragma unroll
        for (int nt = 0; nt < 4; ++nt) {
            int col = colBlock + wn * 32 + nt * 8 + tg * 2;
            float b0 = g_bcat[col], b1 = g_bcat[col + 1];
            int row0 = rowBlock + wm * 64 + mt * 16 + g;
            if (row0 < M) {
                float2 o = make_float2(c[mt][nt][0] + b0, c[mt][nt][1] + b1);
                *(float2*)&g_P[(size_t)row0 * NC + col] = o;
            }
            int row1 = row0 + 8;
            if (row1 < M) {
                float2 o = make_float2(c[mt][nt][2] + b0, c[mt][nt][3] + b1);
                *(float2*)&g_P[(size_t)row1 * NC + col] = o;
            }
        }
    }
}

// ---------------------------------------------------------------------------
// GCN aggregate: one warp per node, unroll 2. Emits tf32 bits.
// ---------------------------------------------------------------------------
__global__ void gcn_agg_kernel(const float* __restrict__ bias, int n) {
    int warp = (blockIdx.x * blockDim.x + threadIdx.x) >> 5;
    int lane = threadIdx.x & 31;
    if (warp >= n) return;
    int i = warp;
    float di = g_dinv[i];

    float4 acc = make_float4(0.f, 0.f, 0.f, 0.f);
    int e0 = g_rowptr[i], e1 = g_rowptr[i + 1];
    int e = e0;
    for (; e + 2 <= e1; e += 2) {
        int s0 = g_csr_src[e];
        int s1 = g_csr_src[e + 1];
        float w0 = g_dinv[s0] * di;
        float w1 = g_dinv[s1] * di;
        float4 v0 = *(const float4*)&g_h0[(size_t)s0 * HDIM + lane * 4];
        float4 v1 = *(const float4*)&g_h0[(size_t)s1 * HDIM + lane * 4];
        acc.x = fmaf(w0, v0.x, acc.x); acc.y = fmaf(w0, v0.y, acc.y);
        acc.z = fmaf(w0, v0.z, acc.z); acc.w = fmaf(w0, v0.w, acc.w);
        acc.x = fmaf(w1, v1.x, acc.x); acc.y = fmaf(w1, v1.y, acc.y);
        acc.z = fmaf(w1, v1.z, acc.z); acc.w = fmaf(w1, v1.w, acc.w);
    }
    if (e < e1) {
        int s0 = g_csr_src[e];
        float w0 = g_dinv[s0] * di;
        float4 v0 = *(const float4*)&g_h0[(size_t)s0 * HDIM + lane * 4];
        acc.x = fmaf(w0, v0.x, acc.x); acc.y = fmaf(w0, v0.y, acc.y);
        acc.z = fmaf(w0, v0.z, acc.z); acc.w = fmaf(w0, v0.w, acc.w);
    }
    {   // self loop
        float w = di * di;
        float4 v = *(const float4*)&g_h0[(size_t)i * HDIM + lane * 4];
        acc.x = fmaf(w, v.x, acc.x); acc.y = fmaf(w, v.y, acc.y);
        acc.z = fmaf(w, v.z, acc.z); acc.w = fmaf(w, v.w, acc.w);
    }
    float4 bb = *(const float4*)&bias[lane * 4];
    acc.x += bb.x; acc.y += bb.y; acc.z += bb.z; acc.w += bb.w;
    acc.x = (acc.x >= 0.f) ? acc.x : 0.01f * acc.x;
    acc.y = (acc.y >= 0.f) ? acc.y : 0.01f * acc.y;
    acc.z = (acc.z >= 0.f) ? acc.z : 0.01f * acc.z;
    acc.w = (acc.w >= 0.f) ? acc.w : 0.01f * acc.w;
    uint4 o;
    o.x = f2tf32(acc.x); o.y = f2tf32(acc.y);
    o.z = f2tf32(acc.z); o.w = f2tf32(acc.w);
    *(uint4*)&g_h[(size_t)i * HDIM + lane * 4] = o;
}

// ---------------------------------------------------------------------------
// Fused TransformerConv (mu + logstd): one warp per dst node, online softmax.
// KV via 2 LDG.128 per lane per edge: kk = (kmu_l, kmu_{l+32}, kls_l, kls_{l+32}),
// vv likewise.
// ---------------------------------------------------------------------------
__global__ void transformer_kernel(float* __restrict__ out, int n) {
    int warp = (blockIdx.x * blockDim.x + threadIdx.x) >> 5;
    int lane = threadIdx.x & 31;
    if (warp >= n) return;
    int i = warp;
    const float2* Pi2 = (const float2*)&g_P[(size_t)i * PDIM];

    float2 qm = Pi2[(OFF_QMU >> 1) + lane];
    float2 ql = Pi2[(OFF_QLS >> 1) + lane];

    float mm = -INFINITY, ml = -INFINITY;
    float sm = 0.f, sl = 0.f;
    float2 am = make_float2(0.f, 0.f);
    float2 al = make_float2(0.f, 0.f);

    int e0 = g_rowptr[i], e1 = g_rowptr[i + 1];
    int e = e0;
    for (; e + 2 <= e1; e += 2) {
        int s0 = g_csr_src[e];
        int s1 = g_csr_src[e + 1];
        const float4* P40 = (const float4*)&g_P[(size_t)s0 * PDIM];
        const float4* P41 = (const float4*)&g_P[(size_t)s1 * PDIM];
        float4 kk0 = P40[(OFF_KK >> 2) + lane];
        float4 kk1 = P41[(OFF_KK >> 2) + lane];
        float4 vv0 = P40[(OFF_VV >> 2) + lane];
        float4 vv1 = P41[(OFF_VV >> 2) + lane];

        float pm0 = qm.x * kk0.x + qm.y * kk0.y;
        float pl0 = ql.x * kk0.z + ql.y * kk0.w;
        float pm1 = qm.x * kk1.x + qm.y * kk1.y;
        float pl1 = ql.x * kk1.z + ql.y * kk1.w;
        #pragma unroll
        for (int off = 16; off; off >>= 1) {
            pm0 += __shfl_xor_sync(0xffffffffu, pm0, off);
            pl0 += __shfl_xor_sync(0xffffffffu, pl0, off);
            pm1 += __shfl_xor_sync(0xffffffffu, pm1, off);
            pl1 += __shfl_xor_sync(0xffffffffu, pl1, off);
        }
        float alm0 = pm0 * 0.125f, all0 = pl0 * 0.125f;
        float alm1 = pm1 * 0.125f, all1 = pl1 * 0.125f;

        {
            float nm = fmaxf(mm, alm0);
            float scale = __expf(mm - nm);
            float p = __expf(alm0 - nm);
            sm = sm * scale + p;
            am.x = am.x * scale + p * vv0.x;
            am.y = am.y * scale + p * vv0.y;
            mm = nm;
        }
        {
            float nm = fmaxf(mm, alm1);
            float scale = __expf(mm - nm);
            float p = __expf(alm1 - nm);
            sm = sm * scale + p;
            am.x = am.x * scale + p * vv1.x;
            am.y = am.y * scale + p * vv1.y;
            mm = nm;
        }
        {
            float nm = fmaxf(ml, all0);
            float scale = __expf(ml - nm);
            float p = __expf(all0 - nm);
            sl = sl * scale + p;
            al.x = al.x * scale + p * vv0.z;
            al.y = al.y * scale + p * vv0.w;
            ml = nm;
        }
        {
            float nm = fmaxf(ml, all1);
            float scale = __expf(ml - nm);
            float p = __expf(all1 - nm);
            sl = sl * scale + p;
            al.x = al.x * scale + p * vv1.z;
            al.y = al.y * scale + p * vv1.w;
            ml = nm;
        }
    }
    if (e < e1) {
        int s0 = g_csr_src[e];
        const float4* P40 = (const float4*)&g_P[(size_t)s0 * PDIM];
        float4 kk0 = P40[(OFF_KK >> 2) + lane];
        float4 vv0 = P40[(OFF_VV >> 2) + lane];
        float pm0 = qm.x * kk0.x + qm.y * kk0.y;
        float pl0 = ql.x * kk0.z + ql.y * kk0.w;
        #pragma unroll
        for (int off = 16; off; off >>= 1) {
            pm0 += __shfl_xor_sync(0xffffffffu, pm0, off);
            pl0 += __shfl_xor_sync(0xffffffffu, pl0, off);
        }
        float alm0 = pm0 * 0.125f, all0 = pl0 * 0.125f;
        {
            float nm = fmaxf(mm, alm0);
            float scale = __expf(mm - nm);
            float p = __expf(alm0 - nm);
            sm = sm * scale + p;
            am.x = am.x * scale + p * vv0.x;
            am.y = am.y * scale + p * vv0.y;
            mm = nm;
        }
        {
            float nm = fmaxf(ml, all0);
            float scale = __expf(ml - nm);
            float p = __expf(all0 - nm);
            sl = sl * scale + p;
            al.x = al.x * scale + p * vv0.z;
            al.y = al.y * scale + p * vv0.w;
            ml = nm;
        }
    }

    float2 smu = Pi2[(OFF_SMU >> 1) + lane];
    float2 sls = Pi2[(OFF_SLS >> 1) + lane];
    size_t nd = (size_t)n * DDIM;
    float rm = 1.0f / (sm + 1e-16f);
    float rl = 1.0f / (sl + 1e-16f);
    out[(size_t)i * DDIM + lane]      = am.x * rm + smu.x;
    out[(size_t)i * DDIM + 32 + lane] = am.y * rm + smu.y;
    out[nd + (size_t)i * DDIM + lane]      = fminf(al.x * rl + sls.x, 10.0f);
    out[nd + (size_t)i * DDIM + 32 + lane] = fminf(al.y * rl + sls.y, 10.0f);
}

// ---------------------------------------------------------------------------
// Launch
// ---------------------------------------------------------------------------
extern "C" void kernel_launch(void* const* d_in, const int* in_sizes, int n_in,
                              void* d_out, int out_size) {
    const float* x     = (const float*)d_in[0];
    const void*  ei    = (const void*)d_in[1];
    const float* W_gcn = (const float*)d_in[2];
    const float* b_gcn = (const float*)d_in[3];
    const float* Wq_mu = (const float*)d_in[4];  const float* bq_mu = (const float*)d_in[5];
    const float* Wk_mu = (const float*)d_in[6];  const float* bk_mu = (const float*)d_in[7];
    const float* Wv_mu = (const float*)d_in[8];  const float* bv_mu = (const float*)d_in[9];
    const float* Ws_mu = (const float*)d_in[10]; const float* bs_mu = (const float*)d_in[11];
    const float* Wq_ls = (const float*)d_in[12]; const float* bq_ls = (const float*)d_in[13];
    const float* Wk_ls = (const float*)d_in[14]; const float* bk_ls = (const float*)d_in[15];
    const float* Wv_ls = (const float*)d_in[16]; const float* bv_ls = (const float*)d_in[17];
    const float* Ws_ls = (const float*)d_in[18]; const float* bs_ls = (const float*)d_in[19];
    float* out = (float*)d_out;

    int n = in_sizes[0] / F_IN;      // 50000
    int e = in_sizes[1] / 2;         // 800000

    cudaFuncSetAttribute(gemm_proj_pipe_kernel,
                         cudaFuncAttributeMaxDynamicSharedMemorySize,
                         PIPE_SMEM_BYTES);

    cudaStream_t s2;
    cudaStreamCreate(&s2);
    cudaEvent_t evFork, evJoin;
    cudaEventCreateWithFlags(&evFork, cudaEventDisableTiming);
    cudaEventCreateWithFlags(&evJoin, cudaEventDisableTiming);

    cudaEventRecord(evFork, 0);
    cudaStreamWaitEvent(s2, evFork, 0);

    // launches 0..2 (side stream)
    detect_dtype_kernel<<<1, 256, 0, s2>>>((const int*)ei, e);
    zero_cnt_kernel<<<(n + 255) / 256, 256, 0, s2>>>(n);
    edge_prep_kernel<<<(e + 255) / 256, 256, 0, s2>>>(ei, e, n);

    // launch 3 (main stream): DIAGNOSTIC quarter-size gemm_proj replica.
    // Reads stale-but-deterministic g_h; g_P is fully overwritten by the real
    // gemm_proj below, so the final output is unaffected. This occupies the
    // launch slot the profiler captures, giving a real gemm_proj profile.
    {
        dim3 dgrid(PDIM / TN, 98);
        gemm_proj_pipe_kernel<<<dgrid, 256, PIPE_SMEM_BYTES>>>(98 * TM);
    }

    // launches 4.. (side stream): rest of CSR build + weight pack
    int nblk = (n + 1023) / 1024;
    scan_pass1_kernel<<<nblk, 1024, 0, s2>>>(n);
    scan_pass2_kernel<<<nblk, 1024, 0, s2>>>(n);
    fill_csr_kernel<<<(e + 255) / 256, 256, 0, s2>>>(e);
    pack_weights_kernel<<<(HDIM * PDIM + 255) / 256, 256, 0, s2>>>(
        Wq_mu, Ws_mu, Wq_ls, Ws_ls, Wk_mu, Wv_mu, Wk_ls, Wv_ls,
        bq_mu, bs_mu, bq_ls, bs_ls, bk_mu, bv_mu, bk_ls, bv_ls);
    cudaEventRecord(evJoin, s2);

    // main stream: h0 = x @ W_gcn (after the diagnostic kernel)
    {
        dim3 grid(HDIM / TN, (n + TM - 1) / TM);
        gemm_xw_kernel<<<grid, 256>>>(x, W_gcn, n);
    }

    cudaStreamWaitEvent(0, evJoin, 0);

    // GCN aggregate + bias + LeakyReLU -> h (tf32 bits)
    gcn_agg_kernel<<<(n + 7) / 8, 256>>>(b_gcn, n);

    // P = h @ Wcat + bcat (real run)
    {
        dim3 grid(PDIM / TN, (n + TM - 1) / TM);
        gemm_proj_pipe_kernel<<<grid, 256, PIPE_SMEM_BYTES>>>(n);
    }

    // Fused TransformerConv (mu + logstd) -> out
    transformer_kernel<<<(n + 7) / 8, 256>>>(out, n);
}

// round 15
// speedup vs baseline: 1.1155x; 1.1155x over previous
#include <cuda_runtime.h>
#include <cuda_bf16.h>
#include <math.h>
#include <stdint.h>

// ---------------------------------------------------------------------------
// Problem constants
// ---------------------------------------------------------------------------
#define NMAX 50000
#define EMAX 800000
#define F_IN 256
#define HDIM 128
#define DDIM 64
#define PDIM 512   // 8 projections x 64

// Packed projection layout within a row of P (word offsets):
//   [0..255]   q/s blocks, pairwise interleave: lane l float2 = dims (l, l+32)
//     QMU @0, SMU @64, QLS @128, SLS @192
//   [256..383] KK block: lane l float4 @ word 256+4l = (kmu_l, kmu_{l+32}, kls_l, kls_{l+32})
//   [384..511] VV block: lane l float4 @ word 384+4l = (vmu_l, vmu_{l+32}, vls_l, vls_{l+32})
#define OFF_QMU 0
#define OFF_SMU 64
#define OFF_QLS 128
#define OFF_SLS 192
#define OFF_KK  256
#define OFF_VV  384

// ---------------------------------------------------------------------------
// Static device scratch
// ---------------------------------------------------------------------------
__device__ int      g_is64;
__device__ int      g_cnt[NMAX];
__device__ int      g_pref[NMAX];
__device__ int      g_bsum[64];
__device__ int      g_rowptr[NMAX + 1];
__device__ int      g_cursor[NMAX];
__device__ int      g_src32[EMAX];
__device__ int      g_dst32[EMAX];
__device__ int      g_csr_src[EMAX];
__device__ float    g_dinv[NMAX];
__device__ float    g_h0[(size_t)NMAX * HDIM];   // x @ W_gcn (fp32)
__device__ uint32_t g_h [(size_t)NMAX * HDIM];   // leaky(agg)+b as tf32 bits
__device__ float    g_P [(size_t)NMAX * PDIM];   // packed projections
__device__ uint32_t g_Wcat[HDIM * PDIM];         // tf32 bits
__device__ float    g_bcat[PDIM];

__device__ __forceinline__ uint32_t f2tf32(float v) {
    uint32_t o;
    asm volatile("cvt.rna.tf32.f32 %0, %1;" : "=r"(o) : "f"(v));
    return o;
}

// ---------------------------------------------------------------------------
// Edge dtype detection
// ---------------------------------------------------------------------------
__global__ void detect_dtype_kernel(const int* __restrict__ w, int e) {
    __shared__ int s[256];
    int t = threadIdx.x;
    int limit = (e < 256) ? e : 256;
    int nz = 0;
    if (t < limit) nz = (w[2 * t + 1] != 0) ? 1 : 0;
    s[t] = nz;
    __syncthreads();
    for (int o = 128; o; o >>= 1) {
        if (t < o) s[t] += s[t + o];
        __syncthreads();
    }
    if (t == 0) g_is64 = (s[0] == 0) ? 1 : 0;
}

__global__ void zero_cnt_kernel(int n) {
    int i = blockIdx.x * blockDim.x + threadIdx.x;
    if (i < n) g_cnt[i] = 0;
}

__global__ void edge_prep_kernel(const void* __restrict__ ei, int e, int n) {
    int idx = blockIdx.x * blockDim.x + threadIdx.x;
    if (idx >= e) return;
    int s, d;
    if (g_is64) {
        const long long* p = (const long long*)ei;
        s = (int)p[idx];
        d = (int)p[idx + e];
    } else {
        const int* p = (const int*)ei;
        s = p[idx];
        d = p[idx + e];
    }
    s = (s < 0) ? 0 : ((s >= n) ? n - 1 : s);
    d = (d < 0) ? 0 : ((d >= n) ? n - 1 : d);
    g_src32[idx] = s;
    g_dst32[idx] = d;
    atomicAdd(&g_cnt[d], 1);
}

// ---------------------------------------------------------------------------
// Parallel scan (2 passes)
// ---------------------------------------------------------------------------
__global__ void scan_pass1_kernel(int n) {
    __shared__ int s[1024];
    int t = threadIdx.x;
    int i = blockIdx.x * 1024 + t;
    int v = (i < n) ? g_cnt[i] : 0;
    s[t] = v;
    __syncthreads();
    #pragma unroll
    for (int off = 1; off < 1024; off <<= 1) {
        int u = 0;
        if (t >= off) u = s[t - off];
        __syncthreads();
        if (t >= off) s[t] += u;
        __syncthreads();
    }
    if (i < n) g_pref[i] = s[t];
    if (t == 1023) g_bsum[blockIdx.x] = s[t];
}

__global__ void scan_pass2_kernel(int n) {
    __shared__ int sboff;
    int b = blockIdx.x;
    int t = threadIdx.x;
    if (t == 0) {
        int acc = 0;
        for (int j = 0; j < b; ++j) acc += g_bsum[j];
        sboff = acc;
    }
    __syncthreads();
    int i = b * 1024 + t;
    if (i < n) {
        int incl = g_pref[i] + sboff;
        int c = g_cnt[i];
        int excl = incl - c;
        g_rowptr[i] = excl;
        g_cursor[i] = excl;
        g_dinv[i] = rsqrtf((float)(c + 1));
        if (i == n - 1) g_rowptr[n] = incl;
    }
}

__global__ void fill_csr_kernel(int e) {
    int idx = blockIdx.x * blockDim.x + threadIdx.x;
    if (idx >= e) return;
    int d = g_dst32[idx];
    int pos = atomicAdd(&g_cursor[d], 1);
    g_csr_src[pos] = g_src32[idx];
}

// Pack weights into the P column layout described above. Wcat as tf32 bits.
__global__ void pack_weights_kernel(
    const float* Wq_mu, const float* Ws_mu, const float* Wq_ls, const float* Ws_ls,
    const float* Wk_mu, const float* Wv_mu, const float* Wk_ls, const float* Wv_ls,
    const float* bq_mu, const float* bs_mu, const float* bq_ls, const float* bs_ls,
    const float* bk_mu, const float* bv_mu, const float* bk_ls, const float* bv_ls) {
    int idx = blockIdx.x * blockDim.x + threadIdx.x;

    auto map_col = [&](int j, int& which, int& c) {
        if (j < 256) {
            int p4 = j / DDIM;            // 0..3 : qmu, smu, qls, sls
            int cp = j % DDIM;
            c = (cp >> 1) + 32 * (cp & 1);
            which = p4;
        } else if (j < 384) {
            int tt = j - 256;
            int l = tt >> 2, r = tt & 3;
            c = l + 32 * (r & 1);
            which = (r < 2) ? 4 : 6;      // kmu : kls
        } else {
            int tt = j - 384;
            int l = tt >> 2, r = tt & 3;
            c = l + 32 * (r & 1);
            which = (r < 2) ? 5 : 7;      // vmu : vls
        }
    };
    const float* Ws[8] = {Wq_mu, Ws_mu, Wq_ls, Ws_ls, Wk_mu, Wv_mu, Wk_ls, Wv_ls};
    const float* bs[8] = {bq_mu, bs_mu, bq_ls, bs_ls, bk_mu, bv_mu, bk_ls, bv_ls};

    if (idx < HDIM * PDIM) {
        int k = idx / PDIM;
        int j = idx % PDIM;
        int which, c;
        map_col(j, which, c);
        g_Wcat[idx] = f2tf32(Ws[which][k * DDIM + c]);
    }
    if (idx < PDIM) {
        int which, c;
        map_col(idx, which, c);
        g_bcat[idx] = bs[which][c];
    }
}

// ---------------------------------------------------------------------------
// Shared MMA helper
// ---------------------------------------------------------------------------
__device__ __forceinline__ void mma_tf32(float* c,
    uint32_t a0, uint32_t a1, uint32_t a2, uint32_t a3,
    uint32_t b0, uint32_t b1) {
    asm volatile(
        "mma.sync.aligned.m16n8k8.row.col.f32.tf32.tf32.f32 "
        "{%0,%1,%2,%3}, {%4,%5,%6,%7}, {%8,%9}, {%0,%1,%2,%3};"
        : "+f"(c[0]), "+f"(c[1]), "+f"(c[2]), "+f"(c[3])
        : "r"(a0), "r"(a1), "r"(a2), "r"(a3), "r"(b0), "r"(b1));
}

// ---------------------------------------------------------------------------
// GEMM #1 (x @ W_gcn): proven engine, fp32 inputs with in-kernel cvt.
// __launch_bounds__(256, 2): cap regs at 128 so 2 CTAs co-reside per SM
// (profile showed regs=142 -> 1 CTA/SM -> occ 12.3%, the real bottleneck).
// ---------------------------------------------------------------------------
#define TM 128
#define TN 128
#define TK 32
#define SROW 136

__device__ __forceinline__ int a_colp(int m) {
    return ((m >> 4) << 4) + ((m & 7) << 1) + ((m >> 3) & 1);
}

__global__ __launch_bounds__(256, 2) void gemm_xw_kernel(
    const float* __restrict__ A, const float* __restrict__ B, int M) {
    __shared__ __align__(16) uint32_t As[TK][SROW];
    __shared__ __align__(16) uint32_t Bs[TK][SROW];
    const int K = F_IN, NC = HDIM;

    int t = threadIdx.x;
    int lane = t & 31;
    int warp = t >> 5;
    int wm = warp >> 2;
    int wn = warp & 3;
    int g  = lane >> 2;
    int tg = lane & 3;

    int rowBlock = blockIdx.y * TM;
    int colBlock = blockIdx.x * TN;

    float c[4][4][4];
    #pragma unroll
    for (int i = 0; i < 4; ++i)
        #pragma unroll
        for (int j = 0; j < 4; ++j)
            #pragma unroll
            for (int k = 0; k < 4; ++k) c[i][j][k] = 0.f;

    for (int k0 = 0; k0 < K; k0 += TK) {
        #pragma unroll
        for (int l = 0; l < 4; ++l) {
            int lin = t + l * 256;
            int ar = lin >> 3;
            int ac = (lin & 7) << 2;
            int grow = rowBlock + ar;
            int cp = a_colp(ar);
            float4 v = make_float4(0.f, 0.f, 0.f, 0.f);
            if (grow < M)
                v = *(const float4*)&A[(size_t)grow * K + k0 + ac];
            As[ac + 0][cp] = f2tf32(v.x);
            As[ac + 1][cp] = f2tf32(v.y);
            As[ac + 2][cp] = f2tf32(v.z);
            As[ac + 3][cp] = f2tf32(v.w);
        }
        #pragma unroll
        for (int l = 0; l < 4; ++l) {
            int lin = t + l * 256;
            int br = lin >> 5;
            int bc = (lin & 31) << 2;
            float4 v = *(const float4*)&B[(size_t)(k0 + br) * NC + colBlock + bc];
            uint4 u;
            u.x = f2tf32(v.x); u.y = f2tf32(v.y);
            u.z = f2tf32(v.z); u.w = f2tf32(v.w);
            *(uint4*)&Bs[br][bc] = u;
        }
        __syncthreads();

        #pragma unroll
        for (int ks = 0; ks < 4; ++ks) {
            int kr = ks * 8 + tg;
            uint32_t a[4][4], b[4][2];
            #pragma unroll
            for (int mt = 0; mt < 4; ++mt) {
                int pcol = (wm * 4 + mt) * 16 + (g << 1);
                uint2 p0 = *(const uint2*)&As[kr][pcol];
                uint2 p1 = *(const uint2*)&As[kr + 4][pcol];
                a[mt][0] = p0.x; a[mt][1] = p0.y;
                a[mt][2] = p1.x; a[mt][3] = p1.y;
            }
            #pragma unroll
            for (int nt = 0; nt < 4; ++nt) {
                int nb = wn * 32 + nt * 8 + g;
                b[nt][0] = Bs[kr][nb];
                b[nt][1] = Bs[kr + 4][nb];
            }
            #pragma unroll
            for (int mt = 0; mt < 4; ++mt)
                #pragma unroll
                for (int nt = 0; nt < 4; ++nt)
                    mma_tf32(c[mt][nt], a[mt][0], a[mt][1], a[mt][2], a[mt][3],
                             b[nt][0], b[nt][1]);
        }
        __syncthreads();
    }

    #pragma unroll
    for (int mt = 0; mt < 4; ++mt) {
        #pragma unroll
        for (int nt = 0; nt < 4; ++nt) {
            int col = colBlock + wn * 32 + nt * 8 + tg * 2;
            int row0 = rowBlock + wm * 64 + mt * 16 + g;
            if (row0 < M) {
                float2 o = make_float2(c[mt][nt][0], c[mt][nt][1]);
                *(float2*)&g_h0[(size_t)row0 * NC + col] = o;
            }
            int row1 = row0 + 8;
            if (row1 < M) {
                float2 o = make_float2(c[mt][nt][2], c[mt][nt][3]);
                *(float2*)&g_h0[(size_t)row1 * NC + col] = o;
            }
        }
    }
}

// ---------------------------------------------------------------------------
// GEMM #2 (h @ Wcat, tf32 bits): 4-buffer cp.async pipeline.
// __launch_bounds__(256, 2) for 2 CTAs/SM (smem 2x75776 = 151.5KB fits).
// ---------------------------------------------------------------------------
#define PK 16
#define A_STR 20
#define B_STR 136
#define NSTAGE (HDIM / PK)      // 8
#define NBUF 4
#define A_BUF_WORDS (TM * A_STR)           // 2560
#define B_BUF_WORDS (PK * B_STR)           // 2176
#define PIPE_SMEM_BYTES (NBUF * (A_BUF_WORDS + B_BUF_WORDS) * 4)

__device__ __forceinline__ void cp_async16(uint32_t dst, const void* src, int srcBytes) {
    asm volatile("cp.async.cg.shared.global [%0], [%1], 16, %2;\n"
                 :: "r"(dst), "l"(src), "r"(srcBytes));
}
__device__ __forceinline__ void cp_commit() {
    asm volatile("cp.async.commit_group;\n");
}

__global__ __launch_bounds__(256, 2) void gemm_proj_pipe_kernel(int M) {
    extern __shared__ __align__(16) uint32_t smem[];
    uint32_t* AsBuf = smem;
    uint32_t* BsBuf = smem + NBUF * A_BUF_WORDS;
    const uint32_t* A = g_h;
    const uint32_t* B = g_Wcat;
    const int K = HDIM, NC = PDIM;

    int t = threadIdx.x;
    int lane = t & 31;
    int warp = t >> 5;
    int wm = warp >> 2;
    int wn = warp & 3;
    int g  = lane >> 2;
    int tg = lane & 3;

    int rowBlock = blockIdx.y * TM;
    int colBlock = blockIdx.x * TN;

    uint32_t asBase = (uint32_t)__cvta_generic_to_shared(AsBuf);
    uint32_t bsBase = (uint32_t)__cvta_generic_to_shared(BsBuf);

    int a_r[2], a_c[2], b_r[2], b_c[2];
    #pragma unroll
    for (int l = 0; l < 2; ++l) {
        int lin = t + l * 256;
        a_r[l] = lin >> 2;
        a_c[l] = (lin & 3) << 2;
        b_r[l] = lin >> 5;
        b_c[l] = (lin & 31) << 2;
    }

    float c[4][4][4];
    #pragma unroll
    for (int i = 0; i < 4; ++i)
        #pragma unroll
        for (int j = 0; j < 4; ++j)
            #pragma unroll
            for (int k = 0; k < 4; ++k) c[i][j][k] = 0.f;

    #pragma unroll
    for (int p = 0; p < 3; ++p) {
        int k0 = p * PK;
        #pragma unroll
        for (int l = 0; l < 2; ++l) {
            int grow = rowBlock + a_r[l];
            int gr = (grow < M) ? grow : (M - 1);
            cp_async16(asBase + (((p * TM + a_r[l]) * A_STR + a_c[l]) << 2),
                       &A[(size_t)gr * K + k0 + a_c[l]], (grow < M) ? 16 : 0);
            cp_async16(bsBase + (((p * PK + b_r[l]) * B_STR + b_c[l]) << 2),
                       &B[(size_t)(k0 + b_r[l]) * NC + colBlock + b_c[l]], 16);
        }
        cp_commit();
    }

    #pragma unroll
    for (int s = 0; s < NSTAGE; ++s) {
        int cur = s & (NBUF - 1);
        asm volatile("cp.async.wait_group 2;\n");
        __syncthreads();

        const uint32_t* Acur = AsBuf + cur * A_BUF_WORDS;
        const uint32_t* Bcur = BsBuf + cur * B_BUF_WORDS;
        #pragma unroll
        for (int ks = 0; ks < 2; ++ks) {
            int kr = ks * 8 + tg;
            uint32_t a[4][4], b[4][2];
            #pragma unroll
            for (int mt = 0; mt < 4; ++mt) {
                int mb = wm * 64 + mt * 16 + g;
                a[mt][0] = Acur[mb * A_STR + kr];
                a[mt][1] = Acur[(mb + 8) * A_STR + kr];
                a[mt][2] = Acur[mb * A_STR + kr + 4];
                a[mt][3] = Acur[(mb + 8) * A_STR + kr + 4];
            }
            #pragma unroll
            for (int nt = 0; nt < 4; ++nt) {
                int nb = wn * 32 + nt * 8 + g;
                b[nt][0] = Bcur[kr * B_STR + nb];
                b[nt][1] = Bcur[(kr + 4) * B_STR + nb];
            }
            #pragma unroll
            for (int mt = 0; mt < 4; ++mt)
                #pragma unroll
                for (int nt = 0; nt < 4; ++nt)
                    mma_tf32(c[mt][nt], a[mt][0], a[mt][1], a[mt][2], a[mt][3],
                             b[nt][0], b[nt][1]);
        }
        __syncthreads();

        if (s + 3 < NSTAGE) {
            int nb_ = (s + 3) & (NBUF - 1);
            int k0 = (s + 3) * PK;
            #pragma unroll
            for (int l = 0; l < 2; ++l) {
                int grow = rowBlock + a_r[l];
                int gr = (grow < M) ? grow : (M - 1);
                cp_async16(asBase + (((nb_ * TM + a_r[l]) * A_STR + a_c[l]) << 2),
                           &A[(size_t)gr * K + k0 + a_c[l]], (grow < M) ? 16 : 0);
                cp_async16(bsBase + (((nb_ * PK + b_r[l]) * B_STR + b_c[l]) << 2),
                           &B[(size_t)(k0 + b_r[l]) * NC + colBlock + b_c[l]], 16);
            }
        }
        cp_commit();
    }

    #pragma unroll
    for (int mt = 0; mt < 4; ++mt) {
        #pragma unroll
        for (int nt = 0; nt < 4; ++nt) {
            int col = colBlock + wn * 32 + nt * 8 + tg * 2;
            float b0 = g_bcat[col], b1 = g_bcat[col + 1];
            int row0 = rowBlock + wm * 64 + mt * 16 + g;
            if (row0 < M) {
                float2 o = make_float2(c[mt][nt][0] + b0, c[mt][nt][1] + b1);
                *(float2*)&g_P[(size_t)row0 * NC + col] = o;
            }
            int row1 = row0 + 8;
            if (row1 < M) {
                float2 o = make_float2(c[mt][nt][2] + b0, c[mt][nt][3] + b1);
                *(float2*)&g_P[(size_t)row1 * NC + col] = o;
            }
        }
    }
}

// ---------------------------------------------------------------------------
// GCN aggregate: one warp per node, unroll 2. Emits tf32 bits.
// ---------------------------------------------------------------------------
__global__ void gcn_agg_kernel(const float* __restrict__ bias, int n) {
    int warp = (blockIdx.x * blockDim.x + threadIdx.x) >> 5;
    int lane = threadIdx.x & 31;
    if (warp >= n) return;
    int i = warp;
    float di = g_dinv[i];

    float4 acc = make_float4(0.f, 0.f, 0.f, 0.f);
    int e0 = g_rowptr[i], e1 = g_rowptr[i + 1];
    int e = e0;
    for (; e + 2 <= e1; e += 2) {
        int s0 = g_csr_src[e];
        int s1 = g_csr_src[e + 1];
        float w0 = g_dinv[s0] * di;
        float w1 = g_dinv[s1] * di;
        float4 v0 = *(const float4*)&g_h0[(size_t)s0 * HDIM + lane * 4];
        float4 v1 = *(const float4*)&g_h0[(size_t)s1 * HDIM + lane * 4];
        acc.x = fmaf(w0, v0.x, acc.x); acc.y = fmaf(w0, v0.y, acc.y);
        acc.z = fmaf(w0, v0.z, acc.z); acc.w = fmaf(w0, v0.w, acc.w);
        acc.x = fmaf(w1, v1.x, acc.x); acc.y = fmaf(w1, v1.y, acc.y);
        acc.z = fmaf(w1, v1.z, acc.z); acc.w = fmaf(w1, v1.w, acc.w);
    }
    if (e < e1) {
        int s0 = g_csr_src[e];
        float w0 = g_dinv[s0] * di;
        float4 v0 = *(const float4*)&g_h0[(size_t)s0 * HDIM + lane * 4];
        acc.x = fmaf(w0, v0.x, acc.x); acc.y = fmaf(w0, v0.y, acc.y);
        acc.z = fmaf(w0, v0.z, acc.z); acc.w = fmaf(w0, v0.w, acc.w);
    }
    {   // self loop
        float w = di * di;
        float4 v = *(const float4*)&g_h0[(size_t)i * HDIM + lane * 4];
        acc.x = fmaf(w, v.x, acc.x); acc.y = fmaf(w, v.y, acc.y);
        acc.z = fmaf(w, v.z, acc.z); acc.w = fmaf(w, v.w, acc.w);
    }
    float4 bb = *(const float4*)&bias[lane * 4];
    acc.x += bb.x; acc.y += bb.y; acc.z += bb.z; acc.w += bb.w;
    acc.x = (acc.x >= 0.f) ? acc.x : 0.01f * acc.x;
    acc.y = (acc.y >= 0.f) ? acc.y : 0.01f * acc.y;
    acc.z = (acc.z >= 0.f) ? acc.z : 0.01f * acc.z;
    acc.w = (acc.w >= 0.f) ? acc.w : 0.01f * acc.w;
    uint4 o;
    o.x = f2tf32(acc.x); o.y = f2tf32(acc.y);
    o.z = f2tf32(acc.z); o.w = f2tf32(acc.w);
    *(uint4*)&g_h[(size_t)i * HDIM + lane * 4] = o;
}

// ---------------------------------------------------------------------------
// Fused TransformerConv (mu + logstd): one warp per dst node, online softmax.
// KV via 2 LDG.128 per lane per edge.
// ---------------------------------------------------------------------------
__global__ void transformer_kernel(float* __restrict__ out, int n) {
    int warp = (blockIdx.x * blockDim.x + threadIdx.x) >> 5;
    int lane = threadIdx.x & 31;
    if (warp >= n) return;
    int i = warp;
    const float2* Pi2 = (const float2*)&g_P[(size_t)i * PDIM];

    float2 qm = Pi2[(OFF_QMU >> 1) + lane];
    float2 ql = Pi2[(OFF_QLS >> 1) + lane];

    float mm = -INFINITY, ml = -INFINITY;
    float sm = 0.f, sl = 0.f;
    float2 am = make_float2(0.f, 0.f);
    float2 al = make_float2(0.f, 0.f);

    int e0 = g_rowptr[i], e1 = g_rowptr[i + 1];
    int e = e0;
    for (; e + 2 <= e1; e += 2) {
        int s0 = g_csr_src[e];
        int s1 = g_csr_src[e + 1];
        const float4* P40 = (const float4*)&g_P[(size_t)s0 * PDIM];
        const float4* P41 = (const float4*)&g_P[(size_t)s1 * PDIM];
        float4 kk0 = P40[(OFF_KK >> 2) + lane];
        float4 kk1 = P41[(OFF_KK >> 2) + lane];
        float4 vv0 = P40[(OFF_VV >> 2) + lane];
        float4 vv1 = P41[(OFF_VV >> 2) + lane];

        float pm0 = qm.x * kk0.x + qm.y * kk0.y;
        float pl0 = ql.x * kk0.z + ql.y * kk0.w;
        float pm1 = qm.x * kk1.x + qm.y * kk1.y;
        float pl1 = ql.x * kk1.z + ql.y * kk1.w;
        #pragma unroll
        for (int off = 16; off; off >>= 1) {
            pm0 += __shfl_xor_sync(0xffffffffu, pm0, off);
            pl0 += __shfl_xor_sync(0xffffffffu, pl0, off);
            pm1 += __shfl_xor_sync(0xffffffffu, pm1, off);
            pl1 += __shfl_xor_sync(0xffffffffu, pl1, off);
        }
        float alm0 = pm0 * 0.125f, all0 = pl0 * 0.125f;
        float alm1 = pm1 * 0.125f, all1 = pl1 * 0.125f;

        {
            float nm = fmaxf(mm, alm0);
            float scale = __expf(mm - nm);
            float p = __expf(alm0 - nm);
            sm = sm * scale + p;
            am.x = am.x * scale + p * vv0.x;
            am.y = am.y * scale + p * vv0.y;
            mm = nm;
        }
        {
            float nm = fmaxf(mm, alm1);
            float scale = __expf(mm - nm);
            float p = __expf(alm1 - nm);
            sm = sm * scale + p;
            am.x = am.x * scale + p * vv1.x;
            am.y = am.y * scale + p * vv1.y;
            mm = nm;
        }
        {
            float nm = fmaxf(ml, all0);
            float scale = __expf(ml - nm);
            float p = __expf(all0 - nm);
            sl = sl * scale + p;
            al.x = al.x * scale + p * vv0.z;
            al.y = al.y * scale + p * vv0.w;
            ml = nm;
        }
        {
            float nm = fmaxf(ml, all1);
            float scale = __expf(ml - nm);
            float p = __expf(all1 - nm);
            sl = sl * scale + p;
            al.x = al.x * scale + p * vv1.z;
            al.y = al.y * scale + p * vv1.w;
            ml = nm;
        }
    }
    if (e < e1) {
        int s0 = g_csr_src[e];
        const float4* P40 = (const float4*)&g_P[(size_t)s0 * PDIM];
        float4 kk0 = P40[(OFF_KK >> 2) + lane];
        float4 vv0 = P40[(OFF_VV >> 2) + lane];
        float pm0 = qm.x * kk0.x + qm.y * kk0.y;
        float pl0 = ql.x * kk0.z + ql.y * kk0.w;
        #pragma unroll
        for (int off = 16; off; off >>= 1) {
            pm0 += __shfl_xor_sync(0xffffffffu, pm0, off);
            pl0 += __shfl_xor_sync(0xffffffffu, pl0, off);
        }
        float alm0 = pm0 * 0.125f, all0 = pl0 * 0.125f;
        {
            float nm = fmaxf(mm, alm0);
            float scale = __expf(mm - nm);
            float p = __expf(alm0 - nm);
            sm = sm * scale + p;
            am.x = am.x * scale + p * vv0.x;
            am.y = am.y * scale + p * vv0.y;
            mm = nm;
        }
        {
            float nm = fmaxf(ml, all0);
            float scale = __expf(ml - nm);
            float p = __expf(all0 - nm);
            sl = sl * scale + p;
            al.x = al.x * scale + p * vv0.z;
            al.y = al.y * scale + p * vv0.w;
            ml = nm;
        }
    }

    float2 smu = Pi2[(OFF_SMU >> 1) + lane];
    float2 sls = Pi2[(OFF_SLS >> 1) + lane];
    size_t nd = (size_t)n * DDIM;
    float rm = 1.0f / (sm + 1e-16f);
    float rl = 1.0f / (sl + 1e-16f);
    out[(size_t)i * DDIM + lane]      = am.x * rm + smu.x;
    out[(size_t)i * DDIM + 32 + lane] = am.y * rm + smu.y;
    out[nd + (size_t)i * DDIM + lane]      = fminf(al.x * rl + sls.x, 10.0f);
    out[nd + (size_t)i * DDIM + 32 + lane] = fminf(al.y * rl + sls.y, 10.0f);
}

// ---------------------------------------------------------------------------
// Launch
// ---------------------------------------------------------------------------
extern "C" void kernel_launch(void* const* d_in, const int* in_sizes, int n_in,
                              void* d_out, int out_size) {
    const float* x     = (const float*)d_in[0];
    const void*  ei    = (const void*)d_in[1];
    const float* W_gcn = (const float*)d_in[2];
    const float* b_gcn = (const float*)d_in[3];
    const float* Wq_mu = (const float*)d_in[4];  const float* bq_mu = (const float*)d_in[5];
    const float* Wk_mu = (const float*)d_in[6];  const float* bk_mu = (const float*)d_in[7];
    const float* Wv_mu = (const float*)d_in[8];  const float* bv_mu = (const float*)d_in[9];
    const float* Ws_mu = (const float*)d_in[10]; const float* bs_mu = (const float*)d_in[11];
    const float* Wq_ls = (const float*)d_in[12]; const float* bq_ls = (const float*)d_in[13];
    const float* Wk_ls = (const float*)d_in[14]; const float* bk_ls = (const float*)d_in[15];
    const float* Wv_ls = (const float*)d_in[16]; const float* bv_ls = (const float*)d_in[17];
    const float* Ws_ls = (const float*)d_in[18]; const float* bs_ls = (const float*)d_in[19];
    float* out = (float*)d_out;

    int n = in_sizes[0] / F_IN;      // 50000
    int e = in_sizes[1] / 2;         // 800000

    cudaFuncSetAttribute(gemm_proj_pipe_kernel,
                         cudaFuncAttributeMaxDynamicSharedMemorySize,
                         PIPE_SMEM_BYTES);

    cudaStream_t s2;
    cudaStreamCreate(&s2);
    cudaEvent_t evFork, evJoin;
    cudaEventCreateWithFlags(&evFork, cudaEventDisableTiming);
    cudaEventCreateWithFlags(&evJoin, cudaEventDisableTiming);

    cudaEventRecord(evFork, 0);
    cudaStreamWaitEvent(s2, evFork, 0);

    // --- side stream: CSR build + weight pack ---
    detect_dtype_kernel<<<1, 256, 0, s2>>>((const int*)ei, e);
    zero_cnt_kernel<<<(n + 255) / 256, 256, 0, s2>>>(n);
    edge_prep_kernel<<<(e + 255) / 256, 256, 0, s2>>>(ei, e, n);
    int nblk = (n + 1023) / 1024;
    scan_pass1_kernel<<<nblk, 1024, 0, s2>>>(n);
    scan_pass2_kernel<<<nblk, 1024, 0, s2>>>(n);
    fill_csr_kernel<<<(e + 255) / 256, 256, 0, s2>>>(e);
    pack_weights_kernel<<<(HDIM * PDIM + 255) / 256, 256, 0, s2>>>(
        Wq_mu, Ws_mu, Wq_ls, Ws_ls, Wk_mu, Wv_mu, Wk_ls, Wv_ls,
        bq_mu, bs_mu, bq_ls, bs_ls, bk_mu, bv_mu, bk_ls, bv_ls);
    cudaEventRecord(evJoin, s2);

    // --- main stream: h0 = x @ W_gcn ---
    {
        dim3 grid(HDIM / TN, (n + TM - 1) / TM);
        gemm_xw_kernel<<<grid, 256>>>(x, W_gcn, n);
    }

    cudaStreamWaitEvent(0, evJoin, 0);

    // GCN aggregate + bias + LeakyReLU -> h (tf32 bits)
    gcn_agg_kernel<<<(n + 7) / 8, 256>>>(b_gcn, n);

    // P = h @ Wcat + bcat
    {
        dim3 grid(PDIM / TN, (n + TM - 1) / TM);
        gemm_proj_pipe_kernel<<<grid, 256, PIPE_SMEM_BYTES>>>(n);
    }

    // Fused TransformerConv (mu + logstd) -> out
    transformer_kernel<<<(n + 7) / 8, 256>>>(out, n);
}